// round 4
// baseline (speedup 1.0000x reference)
#include <cuda_runtime.h>
#include <cstdint>

#define MAX_N 100000
#define IN_DIM 192
#define NEG_SLOPE 0.2f
#define EDGE_ILP 4

// Scratch (allocation-free rule: __device__ globals).
// g_rec[n]  = {xproj0, xproj1, a_src, a_dst}
// g_adst[n] = a_dst (packed copy: 8 nodes/sector -> better L1 hit on gathers)
// g_acc[n]  = {sum e*xp0, sum e*xp1, sum e, pad}
__device__ float4 g_rec[MAX_N];
__device__ float  g_adst[MAX_N];
__device__ float4 g_acc[MAX_N];
__device__ int    g_is64;           // 1 if edge_index is int64, 0 if int32
__device__ unsigned int g_ctr;      // software grid barrier counter

// ---------------------------------------------------------------------------
// Kernel 1: projection + logits + self-loop init + (block 0) dtype detect
// and barrier-counter reset. Persistent warp loop; W in registers.
// ---------------------------------------------------------------------------
__global__ __launch_bounds__(256)
void gat_project_kernel(const float* __restrict__ x,
                        const float* __restrict__ W,        // [IN_DIM,2]
                        const float* __restrict__ att_src,  // [2]
                        const float* __restrict__ att_dst,  // [2]
                        const int* __restrict__ eidx_w,     // edge_index as words
                        int det_nwords,                     // 0 => force is64=1
                        int N)
{
    // --- side duties: block 0, warp 0 ---
    if (blockIdx.x == 0 && threadIdx.x < 32) {
        if (threadIdx.x == 0) g_ctr = 0;
        int notz = 0;
        if (det_nwords > 0) {
            for (int i = threadIdx.x; i < 2048; i += 32) {
                int p = 2 * i + 1;                       // odd 32-bit words
                if (p < det_nwords && eidx_w[p] != 0) notz = 1;
            }
        }
        notz = __any_sync(0xffffffffu, notz);
        if (threadIdx.x == 0) g_is64 = (det_nwords > 0) ? (notz ? 0 : 1) : 1;
    }

    int lane  = threadIdx.x & 31;
    int warp  = (blockIdx.x * blockDim.x + threadIdx.x) >> 5;
    int nwarp = (gridDim.x * blockDim.x) >> 5;

    // W as float4: q covers rows 2q,2q+1 -> {W[2q][0],W[2q][1],W[2q+1][0],W[2q+1][1]}
    const float4* W4 = (const float4*)W;
    float4 w0 = __ldg(W4 + lane);
    float4 w1 = __ldg(W4 + lane + 32);
    float4 w2 = __ldg(W4 + lane + 64);
    float as0 = __ldg(att_src + 0), as1 = __ldg(att_src + 1);
    float ad0 = __ldg(att_dst + 0), ad1 = __ldg(att_dst + 1);

    for (int n = warp; n < N; n += nwarp) {
        const float2* xr = (const float2*)(x + (size_t)n * IN_DIM);
        float2 x0 = __ldg(xr + lane);
        float2 x1 = __ldg(xr + lane + 32);
        float2 x2 = __ldg(xr + lane + 64);

        float p0 = x0.x * w0.x + x0.y * w0.z
                 + x1.x * w1.x + x1.y * w1.z
                 + x2.x * w2.x + x2.y * w2.z;
        float p1 = x0.x * w0.y + x0.y * w0.w
                 + x1.x * w1.y + x1.y * w1.w
                 + x2.x * w2.y + x2.y * w2.w;

#pragma unroll
        for (int off = 16; off > 0; off >>= 1) {
            p0 += __shfl_xor_sync(0xffffffffu, p0, off);
            p1 += __shfl_xor_sync(0xffffffffu, p1, off);
        }

        if (lane == 0) {
            float a_s = p0 * as0 + p1 * as1;
            float a_d = p0 * ad0 + p1 * ad1;
            g_rec[n]  = make_float4(p0, p1, a_s, a_d);
            g_adst[n] = a_d;
            float alpha = a_s + a_d;                 // self-loop edge
            alpha = (alpha >= 0.f) ? alpha : NEG_SLOPE * alpha;
            float ev = __expf(alpha);
            g_acc[n] = make_float4(ev * p0, ev * p1, ev, 0.f);
        }
    }
}

// ---------------------------------------------------------------------------
// Kernel 2 (persistent, all blocks resident): fused edge pass + grid barrier
// + normalize/bias epilogue.
//   alpha = leakyrelu(a_src[s] + a_dst[d]); e = exp(alpha)
//   acc[d] += {e*xp0[s], e*xp1[s], e, 0}  (one red.global.add.v4.f32)
// max-subtraction elided: softmax is scale-invariant; fp32-safe here.
// ---------------------------------------------------------------------------
__global__ __launch_bounds__(256)
void gat_edge_final_kernel(const void* __restrict__ edge_index, int E, int N,
                           float* __restrict__ out,
                           const float* __restrict__ bias)
{
    const int T   = gridDim.x * blockDim.x;
    const int tid = blockIdx.x * blockDim.x + threadIdx.x;
    const int is64 = g_is64;

    // ---- edge phase, ILP=4 strided sub-batches ----
    for (int e0 = tid; e0 < E; e0 += T * EDGE_ILP) {
        int s[EDGE_ILP], d[EDGE_ILP];
#pragma unroll
        for (int i = 0; i < EDGE_ILP; i++) {
            int e = e0 + i * T;
            s[i] = -1; d[i] = -1;
            if (e < E) {
                if (is64) {
                    const long long* ei = (const long long*)edge_index;
                    s[i] = (int)ei[e];
                    d[i] = (int)ei[E + e];
                } else {
                    const int* ei = (const int*)edge_index;
                    s[i] = ei[e];
                    d[i] = ei[E + e];
                }
            }
        }

        float4 rs[EDGE_ILP];
        float  ad[EDGE_ILP];
#pragma unroll
        for (int i = 0; i < EDGE_ILP; i++) {
            if ((unsigned)s[i] < (unsigned)N && (unsigned)d[i] < (unsigned)N) {
                rs[i] = g_rec[s[i]];          // 16B gather
                ad[i] = g_adst[d[i]];         // 4B gather, dense array (L1-friendly)
            }
        }

#pragma unroll
        for (int i = 0; i < EDGE_ILP; i++) {
            if ((unsigned)s[i] < (unsigned)N && (unsigned)d[i] < (unsigned)N) {
                float alpha = rs[i].z + ad[i];
                alpha = (alpha >= 0.f) ? alpha : NEG_SLOPE * alpha;
                float ev = __expf(alpha);
                float v0 = ev * rs[i].x;
                float v1 = ev * rs[i].y;
                asm volatile("red.global.add.v4.f32 [%0], {%1, %2, %3, %4};"
                             :: "l"(&g_acc[d[i]]), "f"(v0), "f"(v1), "f"(ev), "f"(0.f)
                             : "memory");
            }
        }
    }

    // ---- software grid barrier (all blocks resident by construction) ----
    __threadfence();                       // order my REDGs before arrival
    __syncthreads();
    __shared__ unsigned int s_go;
    if (threadIdx.x == 0) {
        unsigned int arrived = atomicAdd(&g_ctr, 1u) + 1u;
        if (arrived < gridDim.x) {
            volatile unsigned int* ctr = &g_ctr;
            while (*ctr < gridDim.x) __nanosleep(64);
        }
        s_go = 1;
    }
    __syncthreads();
    (void)s_go;
    __threadfence();                       // acquire: see all blocks' REDGs

    // ---- epilogue: normalize + bias -> out[N,2] ----
    float b0 = __ldg(bias + 0), b1 = __ldg(bias + 1);
    for (int n = tid; n < N; n += T) {
        float4 a = g_acc[n];
        float inv = 1.0f / (a.z + 1e-16f);
        ((float2*)out)[n] = make_float2(a.x * inv + b0, a.y * inv + b1);
    }
}

// ---------------------------------------------------------------------------
// Input identification by element count (robust to metadata ordering):
//   x = largest; edge_index = 2nd; edge_attr = 3rd (gives E); W = 384;
//   att_src, att_dst, bias = the three size-2 tensors in appearance order.
// ---------------------------------------------------------------------------
extern "C" void kernel_launch(void* const* d_in, const int* in_sizes, int n_in,
                              void* d_out, int out_size)
{
    int i_x = -1, i_eidx = -1, i_attr = -1, i_W = -1;
    int small[3] = {-1, -1, -1};
    int nsmall = 0;
    {
        long long best = -1;
        for (int i = 0; i < n_in; i++)
            if (in_sizes[i] > best) { best = in_sizes[i]; i_x = i; }
        best = -1;
        for (int i = 0; i < n_in; i++)
            if (i != i_x && in_sizes[i] > best) { best = in_sizes[i]; i_eidx = i; }
        best = -1;
        for (int i = 0; i < n_in; i++)
            if (i != i_x && i != i_eidx && in_sizes[i] > best) { best = in_sizes[i]; i_attr = i; }
    }
    for (int i = 0; i < n_in; i++) {
        if (i == i_x || i == i_eidx || i == i_attr) continue;
        if (in_sizes[i] > 16) { i_W = i; }
        else if (nsmall < 3) { small[nsmall++] = i; }
    }

    const float* x       = (const float*)d_in[i_x];
    const void*  eidx    = d_in[i_eidx];
    const float* W       = (const float*)d_in[i_W];
    const float* att_src = (const float*)d_in[small[0]];
    const float* att_dst = (const float*)d_in[small[1]];
    const float* bias    = (const float*)d_in[small[2]];
    float* out           = (float*)d_out;

    int N = in_sizes[i_x] / IN_DIM;
    int E = in_sizes[i_attr];               // edge_attr is [E,1]
    int eidx_elems = in_sizes[i_eidx];

    // dtype: ratio 4 => int64 reported as word count (det_nwords=0 => force 64).
    // ratio 2 => ambiguous; K1 block 0 samples odd words on device.
    int det_nwords = (eidx_elems == 4 * E) ? 0 : (2 * E);

    // K1: persistent warp loop (+ detector + barrier reset)
    gat_project_kernel<<<1184, 256>>>(x, W, att_src, att_dst,
                                      (const int*)eidx, det_nwords, N);

    // K2: persistent fused edge+epilogue; grid sized for guaranteed residency
    int sm_count = 148, max_blocks_per_sm = 4;
    cudaDeviceGetAttribute(&sm_count, cudaDevAttrMultiProcessorCount, 0);
    cudaOccupancyMaxActiveBlocksPerMultiprocessor(&max_blocks_per_sm,
                                                  gat_edge_final_kernel, 256, 0);
    if (max_blocks_per_sm < 1) max_blocks_per_sm = 1;
    int grid2 = sm_count * max_blocks_per_sm;
    int need  = (E + 256 * EDGE_ILP - 1) / (256 * EDGE_ILP);
    if (grid2 > need) grid2 = need;         // don't over-launch tiny work
    if (grid2 < 1) grid2 = 1;
    gat_edge_final_kernel<<<grid2, 256>>>(eidx, E, N, out, bias);
}

// round 6
// speedup vs baseline: 1.0523x; 1.0523x over previous
#include <cuda_runtime.h>
#include <cstdint>

#define MAX_N 100000
#define IN_DIM 192
#define NEG_SLOPE 0.2f
#define EDGE_ILP 4

// Scratch (allocation-free rule: __device__ globals).
// g_rec[n]  = {xproj0, xproj1, a_src, a_dst}
// g_adst[n] = a_dst packed (8 nodes/sector -> better L1 behavior on gathers)
// g_acc[n]  = {sum e*xp0, sum e*xp1, sum e, pad}
__device__ float4 g_rec[MAX_N];
__device__ float  g_adst[MAX_N];
__device__ float4 g_acc[MAX_N];
__device__ int    g_is64;   // 1 if edge_index is int64, 0 if int32

// ---------------------------------------------------------------------------
// Kernel 1: projection + logits + self-loop init; block 0 warp 0 also runs
// the int64/int32 detector (odd 32-bit words all zero <=> int64).
// Persistent warp loop, W hoisted to registers. DRAM-bound (~77 MB of x).
// ---------------------------------------------------------------------------
__global__ __launch_bounds__(256)
void gat_project_kernel(const float* __restrict__ x,
                        const float* __restrict__ W,        // [IN_DIM,2]
                        const float* __restrict__ att_src,  // [2]
                        const float* __restrict__ att_dst,  // [2]
                        const int* __restrict__ eidx_w,     // edge_index as words
                        int det_nwords,                     // 0 => force is64=1
                        int N)
{
    if (blockIdx.x == 0 && threadIdx.x < 32) {
        int notz = 0;
        if (det_nwords > 0) {
            for (int i = threadIdx.x; i < 2048; i += 32) {
                int p = 2 * i + 1;
                if (p < det_nwords && eidx_w[p] != 0) notz = 1;
            }
        }
        notz = __any_sync(0xffffffffu, notz);
        if (threadIdx.x == 0) g_is64 = (det_nwords > 0) ? (notz ? 0 : 1) : 1;
    }

    int lane  = threadIdx.x & 31;
    int warp  = (blockIdx.x * blockDim.x + threadIdx.x) >> 5;
    int nwarp = (gridDim.x * blockDim.x) >> 5;

    // W as float4: q covers rows 2q,2q+1 -> {W[2q][0],W[2q][1],W[2q+1][0],W[2q+1][1]}
    const float4* W4 = (const float4*)W;
    float4 w0 = __ldg(W4 + lane);
    float4 w1 = __ldg(W4 + lane + 32);
    float4 w2 = __ldg(W4 + lane + 64);
    float as0 = __ldg(att_src + 0), as1 = __ldg(att_src + 1);
    float ad0 = __ldg(att_dst + 0), ad1 = __ldg(att_dst + 1);

    for (int n = warp; n < N; n += nwarp) {
        const float2* xr = (const float2*)(x + (size_t)n * IN_DIM);
        float2 x0 = __ldg(xr + lane);
        float2 x1 = __ldg(xr + lane + 32);
        float2 x2 = __ldg(xr + lane + 64);

        float p0 = x0.x * w0.x + x0.y * w0.z
                 + x1.x * w1.x + x1.y * w1.z
                 + x2.x * w2.x + x2.y * w2.z;
        float p1 = x0.x * w0.y + x0.y * w0.w
                 + x1.x * w1.y + x1.y * w1.w
                 + x2.x * w2.y + x2.y * w2.w;

#pragma unroll
        for (int off = 16; off > 0; off >>= 1) {
            p0 += __shfl_xor_sync(0xffffffffu, p0, off);
            p1 += __shfl_xor_sync(0xffffffffu, p1, off);
        }

        if (lane == 0) {
            float a_s = p0 * as0 + p1 * as1;
            float a_d = p0 * ad0 + p1 * ad1;
            g_rec[n]  = make_float4(p0, p1, a_s, a_d);
            g_adst[n] = a_d;
            float alpha = a_s + a_d;                 // self-loop edge
            alpha = (alpha >= 0.f) ? alpha : NEG_SLOPE * alpha;
            float ev = __expf(alpha);
            g_acc[n] = make_float4(ev * p0, ev * p1, ev, 0.f);
        }
    }
}

// ---------------------------------------------------------------------------
// Kernel 2: single fused pass over edges, ILP=4, full grid (18 regs, ~87%
// occ). L1tex-wavefront bound at ~3.5 wf/edge.
//   alpha = leakyrelu(a_src[s] + a_dst[d]); e = exp(alpha)
//   acc[d] += {e*xp0[s], e*xp1[s], e, 0}  via one red.global.add.v4.f32
// (softmax max-subtraction elided: scale-invariant; fp32-safe here)
// ---------------------------------------------------------------------------
__global__ __launch_bounds__(256)
void gat_edge_kernel(const void* __restrict__ edge_index, int E, int N)
{
    int base = blockIdx.x * (256 * EDGE_ILP) + threadIdx.x;
    int is64 = g_is64;

    int s[EDGE_ILP], d[EDGE_ILP];
#pragma unroll
    for (int i = 0; i < EDGE_ILP; i++) {
        int e = base + i * 256;
        s[i] = -1; d[i] = -1;
        if (e < E) {
            if (is64) {
                const long long* ei = (const long long*)edge_index;
                s[i] = (int)__ldg(ei + e);
                d[i] = (int)__ldg(ei + E + e);
            } else {
                const int* ei = (const int*)edge_index;
                s[i] = __ldg(ei + e);
                d[i] = __ldg(ei + E + e);
            }
        }
    }

    float4 rs[EDGE_ILP];
    float  ad[EDGE_ILP];
#pragma unroll
    for (int i = 0; i < EDGE_ILP; i++) {
        if ((unsigned)s[i] < (unsigned)N && (unsigned)d[i] < (unsigned)N) {
            rs[i] = __ldg(&g_rec[s[i]]);        // 16B gather, read-only path
            ad[i] = __ldg(&g_adst[d[i]]);       // 4B gather, dense array
        }
    }

#pragma unroll
    for (int i = 0; i < EDGE_ILP; i++) {
        if ((unsigned)s[i] < (unsigned)N && (unsigned)d[i] < (unsigned)N) {
            float alpha = rs[i].z + ad[i];
            alpha = (alpha >= 0.f) ? alpha : NEG_SLOPE * alpha;
            float ev = __expf(alpha);
            float v0 = ev * rs[i].x;
            float v1 = ev * rs[i].y;
            asm volatile("red.global.add.v4.f32 [%0], {%1, %2, %3, %4};"
                         :: "l"(&g_acc[d[i]]), "f"(v0), "f"(v1), "f"(ev), "f"(0.f)
                         : "memory");
        }
    }
}

// ---------------------------------------------------------------------------
// Kernel 3: normalize + bias -> out[N,2]. 128-thread blocks for better SM
// coverage on this tiny, launch/tail-bound kernel.
// ---------------------------------------------------------------------------
__global__ __launch_bounds__(128)
void gat_final_kernel(float* __restrict__ out,
                      const float* __restrict__ bias,
                      int N)
{
    int n = blockIdx.x * blockDim.x + threadIdx.x;
    if (n >= N) return;
    float4 a = g_acc[n];
    float inv = 1.0f / (a.z + 1e-16f);
    float b0 = __ldg(bias + 0), b1 = __ldg(bias + 1);
    ((float2*)out)[n] = make_float2(a.x * inv + b0, a.y * inv + b1);
}

// ---------------------------------------------------------------------------
// Input identification by element count (robust to metadata ordering):
//   x = largest; edge_index = 2nd; edge_attr = 3rd (gives E); W = 384;
//   att_src, att_dst, bias = the three size-2 tensors in appearance order.
// ---------------------------------------------------------------------------
extern "C" void kernel_launch(void* const* d_in, const int* in_sizes, int n_in,
                              void* d_out, int out_size)
{
    int i_x = -1, i_eidx = -1, i_attr = -1, i_W = -1;
    int small[3] = {-1, -1, -1};
    int nsmall = 0;
    {
        long long best = -1;
        for (int i = 0; i < n_in; i++)
            if (in_sizes[i] > best) { best = in_sizes[i]; i_x = i; }
        best = -1;
        for (int i = 0; i < n_in; i++)
            if (i != i_x && in_sizes[i] > best) { best = in_sizes[i]; i_eidx = i; }
        best = -1;
        for (int i = 0; i < n_in; i++)
            if (i != i_x && i != i_eidx && in_sizes[i] > best) { best = in_sizes[i]; i_attr = i; }
    }
    for (int i = 0; i < n_in; i++) {
        if (i == i_x || i == i_eidx || i == i_attr) continue;
        if (in_sizes[i] > 16) { i_W = i; }
        else if (nsmall < 3) { small[nsmall++] = i; }
    }

    const float* x       = (const float*)d_in[i_x];
    const void*  eidx    = d_in[i_eidx];
    const float* W       = (const float*)d_in[i_W];
    const float* att_src = (const float*)d_in[small[0]];
    const float* att_dst = (const float*)d_in[small[1]];
    const float* bias    = (const float*)d_in[small[2]];
    float* out           = (float*)d_out;

    int N = in_sizes[i_x] / IN_DIM;
    int E = in_sizes[i_attr];               // edge_attr is [E,1]
    int eidx_elems = in_sizes[i_eidx];

    // dtype: ratio 4 => int64 reported as word count (det_nwords=0 => force 64).
    // ratio 2 => ambiguous; K1 block 0 samples odd words on device.
    int det_nwords = (eidx_elems == 4 * E) ? 0 : (2 * E);

    // K1: persistent warp loop (+ detector)
    gat_project_kernel<<<1184, 256>>>(x, W, att_src, att_dst,
                                      (const int*)eidx, det_nwords, N);

    // K2: ILP=4 edges per thread, full grid (max occupancy)
    int blocks2 = (E + 256 * EDGE_ILP - 1) / (256 * EDGE_ILP);
    gat_edge_kernel<<<blocks2, 256>>>(eidx, E, N);

    // K3: normalize + bias
    gat_final_kernel<<<(N + 127) / 128, 128>>>(out, bias, N);
}